// round 1
// baseline (speedup 1.0000x reference)
#include <cuda_runtime.h>
#include <math.h>

#define NPTS (96*96*96)          // 884736 points per sample
#define NB   64
#define HB   (NB*NB)
#define SH_STRIDE 65             // padded row stride in smem to spread banks
#define CEXP 2.0639959687578734f // alpha*h^2 = 8192/3969

__device__ float        g_hist[2][HB];
__device__ unsigned int g_mm[8];   // [sample*4 + {tmin,tmax,smin,smax}] as orderable keys

__device__ __forceinline__ unsigned fkey(float x){
    unsigned u = __float_as_uint(x);
    return (u & 0x80000000u) ? ~u : (u | 0x80000000u);
}
__device__ __forceinline__ float funkey(unsigned u){
    return (u & 0x80000000u) ? __uint_as_float(u ^ 0x80000000u) : __uint_as_float(~u);
}

__global__ void k_init(){
    int tid = threadIdx.x;
    float* h = &g_hist[0][0];
    for (int i = tid; i < 2*HB; i += blockDim.x) h[i] = 0.f;
    if (tid < 8) g_mm[tid] = (tid & 1) ? 0u : 0xFFFFFFFFu;
}

__global__ void __launch_bounds__(256) k_minmax(const float4* __restrict__ tar,
                                                const float4* __restrict__ src){
    int s = blockIdx.y;
    const float4* t4 = tar + (size_t)s * (NPTS/4);
    const float4* s4 = src + (size_t)s * (NPTS/4);
    float tmn =  3.4e38f, tmx = -3.4e38f, smn = 3.4e38f, smx = -3.4e38f;
    int idx    = blockIdx.x * blockDim.x + threadIdx.x;
    int stride = gridDim.x * blockDim.x;
    for (; idx < NPTS/4; idx += stride){
        float4 a = t4[idx]; float4 b = s4[idx];
        tmn = fminf(tmn, fminf(fminf(a.x,a.y), fminf(a.z,a.w)));
        tmx = fmaxf(tmx, fmaxf(fmaxf(a.x,a.y), fmaxf(a.z,a.w)));
        smn = fminf(smn, fminf(fminf(b.x,b.y), fminf(b.z,b.w)));
        smx = fmaxf(smx, fmaxf(fmaxf(b.x,b.y), fmaxf(b.z,b.w)));
    }
    #pragma unroll
    for (int o = 16; o; o >>= 1){
        tmn = fminf(tmn, __shfl_xor_sync(0xFFFFFFFFu, tmn, o));
        tmx = fmaxf(tmx, __shfl_xor_sync(0xFFFFFFFFu, tmx, o));
        smn = fminf(smn, __shfl_xor_sync(0xFFFFFFFFu, smn, o));
        smx = fmaxf(smx, __shfl_xor_sync(0xFFFFFFFFu, smx, o));
    }
    if ((threadIdx.x & 31) == 0){
        atomicMin(&g_mm[s*4+0], fkey(tmn));
        atomicMax(&g_mm[s*4+1], fkey(tmx));
        atomicMin(&g_mm[s*4+2], fkey(smn));
        atomicMax(&g_mm[s*4+3], fkey(smx));
    }
}

__global__ void __launch_bounds__(512) k_hist(const float4* __restrict__ tar,
                                              const float4* __restrict__ src){
    __shared__ float sh[NB * SH_STRIDE];
    const int tid = threadIdx.x;
    const int s   = blockIdx.y;
    for (int i = tid; i < NB * SH_STRIDE; i += 512) sh[i] = 0.f;
    __syncthreads();

    const float tmin = funkey(g_mm[s*4+0]);
    const float tmax = funkey(g_mm[s*4+1]);
    const float smin = funkey(g_mm[s*4+2]);
    const float smax = funkey(g_mm[s*4+3]);
    const float tsc = 63.0f / (tmax - tmin + 1e-10f);
    const float ssc = 63.0f / (smax - smin + 1e-10f);

    const float4* t4 = tar + (size_t)s * (NPTS/4);
    const float4* s4 = src + (size_t)s * (NPTS/4);

    int idx    = blockIdx.x * 512 + tid;
    int stride = gridDim.x * 512;
    for (; idx < NPTS/4; idx += stride){
        float4 a = t4[idx];
        float4 b = s4[idx];
        float tv4[4] = {a.x, a.y, a.z, a.w};
        float sv4[4] = {b.x, b.y, b.z, b.w};
        #pragma unroll
        for (int e = 0; e < 4; e++){
            float ut = (tv4[e] - tmin) * tsc;
            float us = (sv4[e] - smin) * ssc;
            int kt = __float2int_rn(ut);
            int ks = __float2int_rn(us);
            float dt = ut - (float)kt;
            float ds = us - (float)ks;
            float wt[5], ws[5];
            #pragma unroll
            for (int j = 0; j < 5; j++){
                float o  = (float)(j - 2);
                float x1 = dt - o;
                float x2 = ds - o;
                wt[j] = ((unsigned)(kt + j - 2) < 64u) ? __expf(-CEXP * x1 * x1) : 0.f;
                ws[j] = ((unsigned)(ks + j - 2) < 64u) ? __expf(-CEXP * x2 * x2) : 0.f;
            }
            int base = (kt - 2) * SH_STRIDE + (ks - 2);
            #pragma unroll
            for (int jt = 0; jt < 5; jt++){
                if (wt[jt] != 0.f){
                    #pragma unroll
                    for (int js = 0; js < 5; js++){
                        if (ws[js] != 0.f)
                            atomicAdd(&sh[base + jt * SH_STRIDE + js], wt[jt] * ws[js]);
                    }
                }
            }
        }
    }
    __syncthreads();
    for (int i = tid; i < HB; i += 512){
        int r = i >> 6, c = i & 63;
        atomicAdd(&g_hist[s][i], sh[r * SH_STRIDE + c]);
    }
}

__global__ void __launch_bounds__(256) k_final(float* __restrict__ out){
    __shared__ double red[256];
    __shared__ float  marg[128];
    __shared__ double sS, sEJ;
    const int tid = threadIdx.x;
    double ratio_sum = 0.0;

    for (int s = 0; s < 2; s++){
        const float* h = g_hist[s];

        // total mass
        double acc = 0.0;
        for (int i = tid; i < HB; i += 256) acc += (double)h[i];
        red[tid] = acc; __syncthreads();
        for (int o = 128; o; o >>= 1){ if (tid < o) red[tid] += red[tid + o]; __syncthreads(); }
        if (tid == 0) sS = red[0];
        __syncthreads();
        float S = (float)sS;

        // joint entropy
        double ej = 0.0;
        for (int i = tid; i < HB; i += 256){
            float p = h[i] / S;
            ej -= (double)(p * logf(p + 1e-10f));
        }
        red[tid] = ej; __syncthreads();
        for (int o = 128; o; o >>= 1){ if (tid < o) red[tid] += red[tid + o]; __syncthreads(); }
        if (tid == 0) sEJ = red[0];
        __syncthreads();

        // marginals (rows 0..63 -> p_tar, cols 0..63 -> p_src)
        if (tid < 64){
            float rs = 0.f;
            for (int c = 0; c < 64; c++) rs += h[tid * 64 + c];
            marg[tid] = rs;
        } else if (tid < 128){
            int c = tid - 64;
            float cs = 0.f;
            for (int b = 0; b < 64; b++) cs += h[b * 64 + c];
            marg[tid] = cs;
        }
        __syncthreads();

        double em = 0.0;
        if (tid < 128){
            float p = marg[tid] / S;
            em = -(double)(p * logf(p + 1e-10f));
        }
        red[tid] = em; __syncthreads();
        for (int o = 128; o; o >>= 1){ if (tid < o) red[tid] += red[tid + o]; __syncthreads(); }
        if (tid == 0) ratio_sum += red[0] / sEJ;   // (ent_tar + ent_src) / ent_joint
        __syncthreads();
    }

    if (tid == 0) out[0] = (float)(-(ratio_sum * 0.5));
}

extern "C" void kernel_launch(void* const* d_in, const int* in_sizes, int n_in,
                              void* d_out, int out_size){
    const float* tar = (const float*)d_in[0];
    const float* src = (const float*)d_in[1];
    float* out = (float*)d_out;

    k_init<<<1, 256>>>();

    dim3 gmm(128, 2);
    k_minmax<<<gmm, 256>>>((const float4*)tar, (const float4*)src);

    dim3 gh(144, 2);
    k_hist<<<gh, 512>>>((const float4*)tar, (const float4*)src);

    k_final<<<1, 256>>>(out);
}

// round 2
// speedup vs baseline: 1.4382x; 1.4382x over previous
#include <cuda_runtime.h>
#include <math.h>

#define NPTS (96*96*96)          // 884736 points per sample
#define NB   64
#define HB   (NB*NB)
#define SH_STRIDE 65             // padded row stride in smem
#define CEXP 2.0639959687578734f // 1/(2*sigma_bins^2) = 8192/3969, sigma = 0.5 bin

__device__ float        g_hist[2][HB];   // zero-initialized at module load
__device__ unsigned int g_mm[8] = {0xFFFFFFFFu, 0u, 0xFFFFFFFFu, 0u,
                                   0xFFFFFFFFu, 0u, 0xFFFFFFFFu, 0u};

__device__ __forceinline__ unsigned fkey(float x){
    unsigned u = __float_as_uint(x);
    return (u & 0x80000000u) ? ~u : (u | 0x80000000u);
}
__device__ __forceinline__ float funkey(unsigned u){
    return (u & 0x80000000u) ? __uint_as_float(u ^ 0x80000000u) : __uint_as_float(~u);
}
__device__ __forceinline__ float wred(float v){
    #pragma unroll
    for (int o = 16; o; o >>= 1) v += __shfl_xor_sync(0xFFFFFFFFu, v, o);
    return v;
}

// ---------------- min/max ----------------
__global__ void __launch_bounds__(512) k_minmax(const float4* __restrict__ tar,
                                                const float4* __restrict__ src){
    int s = blockIdx.y;
    const float4* t4 = tar + (size_t)s * (NPTS/4);
    const float4* s4 = src + (size_t)s * (NPTS/4);
    float tmn =  3.4e38f, tmx = -3.4e38f, smn = 3.4e38f, smx = -3.4e38f;
    int idx    = blockIdx.x * blockDim.x + threadIdx.x;
    int stride = gridDim.x * blockDim.x;
    for (; idx < NPTS/4; idx += stride){
        float4 a = t4[idx]; float4 b = s4[idx];
        tmn = fminf(tmn, fminf(fminf(a.x,a.y), fminf(a.z,a.w)));
        tmx = fmaxf(tmx, fmaxf(fmaxf(a.x,a.y), fmaxf(a.z,a.w)));
        smn = fminf(smn, fminf(fminf(b.x,b.y), fminf(b.z,b.w)));
        smx = fmaxf(smx, fmaxf(fmaxf(b.x,b.y), fmaxf(b.z,b.w)));
    }
    #pragma unroll
    for (int o = 16; o; o >>= 1){
        tmn = fminf(tmn, __shfl_xor_sync(0xFFFFFFFFu, tmn, o));
        tmx = fmaxf(tmx, __shfl_xor_sync(0xFFFFFFFFu, tmx, o));
        smn = fminf(smn, __shfl_xor_sync(0xFFFFFFFFu, smn, o));
        smx = fmaxf(smx, __shfl_xor_sync(0xFFFFFFFFu, smx, o));
    }
    if ((threadIdx.x & 31) == 0){
        atomicMin(&g_mm[s*4+0], fkey(tmn));
        atomicMax(&g_mm[s*4+1], fkey(tmx));
        atomicMin(&g_mm[s*4+2], fkey(smn));
        atomicMax(&g_mm[s*4+3], fkey(smx));
    }
}

// ---------------- joint histogram (4x4 floor-anchored stencil) ----------------
__global__ void __launch_bounds__(512) k_hist(const float4* __restrict__ tar,
                                              const float4* __restrict__ src){
    __shared__ float sh[NB * SH_STRIDE];
    const int tid = threadIdx.x;
    const int s   = blockIdx.y;
    for (int i = tid; i < NB * SH_STRIDE; i += 512) sh[i] = 0.f;
    __syncthreads();

    const float tmin = funkey(g_mm[s*4+0]);
    const float tmax = funkey(g_mm[s*4+1]);
    const float smin = funkey(g_mm[s*4+2]);
    const float smax = funkey(g_mm[s*4+3]);
    const float tsc = 63.0f / (tmax - tmin + 1e-10f);
    const float ssc = 63.0f / (smax - smin + 1e-10f);

    const float4* t4 = tar + (size_t)s * (NPTS/4);
    const float4* s4 = src + (size_t)s * (NPTS/4);

    int idx    = blockIdx.x * 512 + tid;
    int stride = gridDim.x * 512;
    for (; idx < NPTS/4; idx += stride){
        float4 a = t4[idx];
        float4 b = s4[idx];
        float tv4[4] = {a.x, a.y, a.z, a.w};
        float sv4[4] = {b.x, b.y, b.z, b.w};
        #pragma unroll
        for (int e = 0; e < 4; e++){
            float ut = (tv4[e] - tmin) * tsc;
            float us = (sv4[e] - smin) * ssc;
            int kt = __float2int_rd(ut);
            int ks = __float2int_rd(us);
            float dt = ut - (float)kt;
            float ds = us - (float)ks;
            float wt[4], ws[4];
            #pragma unroll
            for (int j = 0; j < 4; j++){
                float x1 = dt - (float)(j - 1);
                float x2 = ds - (float)(j - 1);
                wt[j] = ((unsigned)(kt + j - 1) < 64u) ? __expf(-CEXP * x1 * x1) : 0.f;
                ws[j] = ((unsigned)(ks + j - 1) < 64u) ? __expf(-CEXP * x2 * x2) : 0.f;
            }
            int base = (kt - 1) * SH_STRIDE + (ks - 1);
            #pragma unroll
            for (int jt = 0; jt < 4; jt++){
                if (wt[jt] != 0.f){
                    #pragma unroll
                    for (int js = 0; js < 4; js++){
                        if (ws[js] != 0.f)
                            atomicAdd(&sh[base + jt * SH_STRIDE + js], wt[jt] * ws[js]);
                    }
                }
            }
        }
    }
    __syncthreads();
    for (int i = tid; i < HB; i += 512){
        int r = i >> 6, c = i & 63;
        atomicAdd(&g_hist[s][i], sh[r * SH_STRIDE + c]);   // compiles to RED
    }
}

// ---------------- entropies + loss + state reset ----------------
__global__ void __launch_bounds__(512) k_final(float* __restrict__ out){
    __shared__ float red[2][16];
    __shared__ float mrow[2][64];
    __shared__ float mcol[2][64];
    __shared__ float sS[2], sEJ[2];

    const int tid  = threadIdx.x;
    const int lane = tid & 31;
    const int wid  = tid >> 5;

    if (tid < 128){
        (&mrow[0][0])[tid] = 0.f;
        (&mcol[0][0])[tid] = 0.f;
    }

    // Each thread owns 8 contiguous bins per sample (one row fragment).
    float v[2][8];
    float ls[2];
    #pragma unroll
    for (int s = 0; s < 2; s++){
        const float4* h4 = (const float4*)g_hist[s];
        float4 a = h4[tid*2], b = h4[tid*2+1];
        v[s][0]=a.x; v[s][1]=a.y; v[s][2]=a.z; v[s][3]=a.w;
        v[s][4]=b.x; v[s][5]=b.y; v[s][6]=b.z; v[s][7]=b.w;
        ls[s] = ((a.x+a.y)+(a.z+a.w)) + ((b.x+b.y)+(b.z+b.w));
    }
    __syncthreads();   // marginal buffers zeroed

    // marginals via smem atomics (rotation makes col updates conflict-free)
    const int row = tid >> 3;
    const int c0  = (tid & 7) * 8;
    const int rot = (tid >> 3) & 7;
    #pragma unroll
    for (int s = 0; s < 2; s++){
        atomicAdd(&mrow[s][row], ls[s]);
        #pragma unroll
        for (int j = 0; j < 8; j++){
            int jj = (j + rot) & 7;
            atomicAdd(&mcol[s][c0 + jj], v[s][jj]);
        }
    }

    // total mass S per sample
    float s0 = wred(ls[0]);
    float s1 = wred(ls[1]);
    if (lane == 0){ red[0][wid] = s0; red[1][wid] = s1; }
    __syncthreads();
    if (tid == 0){
        float t0 = 0.f, t1 = 0.f;
        #pragma unroll
        for (int i = 0; i < 16; i++){ t0 += red[0][i]; t1 += red[1][i]; }
        sS[0] = t0; sS[1] = t1;
    }
    __syncthreads();

    // joint entropy from register-resident bins
    #pragma unroll
    for (int s = 0; s < 2; s++){
        float invS = 1.0f / sS[s];
        float acc = 0.f;
        #pragma unroll
        for (int k = 0; k < 8; k++){
            float p = v[s][k] * invS;
            acc -= p * __logf(p + 1e-10f);
        }
        acc = wred(acc);
        if (lane == 0) red[s][wid] = acc;
    }
    __syncthreads();
    if (tid == 0){
        float e0 = 0.f, e1 = 0.f;
        #pragma unroll
        for (int i = 0; i < 16; i++){ e0 += red[0][i]; e1 += red[1][i]; }
        sEJ[0] = e0; sEJ[1] = e1;
    }
    __syncthreads();   // marginal atomics also complete by here

    // marginal entropies: tid<128 -> sample0, 128..255 -> sample1
    float em = 0.f;
    if (tid < 256){
        int s = tid >> 7, i = tid & 127;
        float m = (i < 64) ? mrow[s][i] : mcol[s][i - 64];
        float p = m / sS[s];
        em = -p * __logf(p + 1e-10f);
    }
    em = wred(em);
    if (lane == 0) red[0][wid] = em;   // warps 0-3: s=0, warps 4-7: s=1
    __syncthreads();
    if (tid == 0){
        float em0 = red[0][0]+red[0][1]+red[0][2]+red[0][3];
        float em1 = red[0][4]+red[0][5]+red[0][6]+red[0][7];
        float ratio = em0 / sEJ[0] + em1 / sEJ[1];
        out[0] = -(0.5f * ratio);
    }

    // reset device state for the next (graph-replayed) invocation
    float4 z = make_float4(0.f, 0.f, 0.f, 0.f);
    float4* h4 = (float4*)&g_hist[0][0];
    #pragma unroll
    for (int k = 0; k < 4; k++) h4[tid * 4 + k] = z;
    if (tid < 8) g_mm[tid] = (tid & 1) ? 0u : 0xFFFFFFFFu;
}

extern "C" void kernel_launch(void* const* d_in, const int* in_sizes, int n_in,
                              void* d_out, int out_size){
    const float* tar = (const float*)d_in[0];
    const float* src = (const float*)d_in[1];
    float* out = (float*)d_out;

    dim3 gmm(148, 2);
    k_minmax<<<gmm, 512>>>((const float4*)tar, (const float4*)src);

    dim3 gh(144, 2);
    k_hist<<<gh, 512>>>((const float4*)tar, (const float4*)src);

    k_final<<<1, 512>>>(out);
}

// round 3
// speedup vs baseline: 1.6276x; 1.1317x over previous
#include <cuda_runtime.h>
#include <math.h>

#define NPTS (96*96*96)          // 884736 points per sample; NPTS/4 = 221184
#define NB   64
#define HB   (NB*NB)
#define SH_STRIDE 65
#define CEXP 2.0639959687578734f // 1/(2*sigma_bins^2) = 8192/3969, sigma = 0.5 bin

// exact factorizations of NPTS/4
#define MM_BLK   54
#define MM_ITER  8               // 54*512*8  = 221184
#define HI_BLK   144
#define HI_ITER  3               // 144*512*3 = 221184

__device__ float        g_hist[2][HB];   // zero-initialized at module load
__device__ unsigned int g_mm[8] = {0xFFFFFFFFu, 0u, 0xFFFFFFFFu, 0u,
                                   0xFFFFFFFFu, 0u, 0xFFFFFFFFu, 0u};

__device__ __forceinline__ unsigned fkey(float x){
    unsigned u = __float_as_uint(x);
    return (u & 0x80000000u) ? ~u : (u | 0x80000000u);
}
__device__ __forceinline__ float funkey(unsigned u){
    return (u & 0x80000000u) ? __uint_as_float(u ^ 0x80000000u) : __uint_as_float(~u);
}
__device__ __forceinline__ float wred(float v){
    #pragma unroll
    for (int o = 16; o; o >>= 1) v += __shfl_xor_sync(0xFFFFFFFFu, v, o);
    return v;
}

// ---------------- min/max: fixed trip count, deep MLP ----------------
__global__ void __launch_bounds__(512) k_minmax(const float4* __restrict__ tar,
                                                const float4* __restrict__ src){
    const int s = blockIdx.y;
    const float4* t4 = tar + (size_t)s * (NPTS/4);
    const float4* s4 = src + (size_t)s * (NPTS/4);
    const int base = blockIdx.x * 512 + threadIdx.x;   // stride = 54*512 = 27648

    float4 ta[MM_ITER], sa[MM_ITER];
    #pragma unroll
    for (int k = 0; k < MM_ITER; k++){
        ta[k] = __ldg(&t4[base + k * (MM_BLK*512)]);
        sa[k] = __ldg(&s4[base + k * (MM_BLK*512)]);
    }

    float tmn =  3.4e38f, tmx = -3.4e38f, smn = 3.4e38f, smx = -3.4e38f;
    #pragma unroll
    for (int k = 0; k < MM_ITER; k++){
        float4 a = ta[k], b = sa[k];
        tmn = fminf(tmn, fminf(fminf(a.x,a.y), fminf(a.z,a.w)));
        tmx = fmaxf(tmx, fmaxf(fmaxf(a.x,a.y), fmaxf(a.z,a.w)));
        smn = fminf(smn, fminf(fminf(b.x,b.y), fminf(b.z,b.w)));
        smx = fmaxf(smx, fmaxf(fmaxf(b.x,b.y), fmaxf(b.z,b.w)));
    }
    #pragma unroll
    for (int o = 16; o; o >>= 1){
        tmn = fminf(tmn, __shfl_xor_sync(0xFFFFFFFFu, tmn, o));
        tmx = fmaxf(tmx, __shfl_xor_sync(0xFFFFFFFFu, tmx, o));
        smn = fminf(smn, __shfl_xor_sync(0xFFFFFFFFu, smn, o));
        smx = fmaxf(smx, __shfl_xor_sync(0xFFFFFFFFu, smx, o));
    }
    if ((threadIdx.x & 31) == 0){
        atomicMin(&g_mm[s*4+0], fkey(tmn));
        atomicMax(&g_mm[s*4+1], fkey(tmx));
        atomicMin(&g_mm[s*4+2], fkey(smn));
        atomicMax(&g_mm[s*4+3], fkey(smx));
    }
}

// ---------------- joint histogram (4x4 floor stencil, fixed trips) ----------------
__global__ void __launch_bounds__(512) k_hist(const float4* __restrict__ tar,
                                              const float4* __restrict__ src){
    __shared__ float sh[NB * SH_STRIDE];
    const int tid = threadIdx.x;
    const int s   = blockIdx.y;
    #pragma unroll
    for (int i = 0; i < 9; i++){
        int j = tid + i * 512;
        if (j < NB * SH_STRIDE) sh[j] = 0.f;
    }
    __syncthreads();

    const float tmin = funkey(g_mm[s*4+0]);
    const float tmax = funkey(g_mm[s*4+1]);
    const float smin = funkey(g_mm[s*4+2]);
    const float smax = funkey(g_mm[s*4+3]);
    const float tsc = 63.0f / (tmax - tmin + 1e-10f);
    const float ssc = 63.0f / (smax - smin + 1e-10f);

    const float4* t4 = tar + (size_t)s * (NPTS/4);
    const float4* s4 = src + (size_t)s * (NPTS/4);
    const int base = blockIdx.x * 512 + tid;           // stride = 144*512 = 73728

    float4 ta[HI_ITER], sa[HI_ITER];
    #pragma unroll
    for (int k = 0; k < HI_ITER; k++){
        ta[k] = __ldg(&t4[base + k * (HI_BLK*512)]);
        sa[k] = __ldg(&s4[base + k * (HI_BLK*512)]);
    }

    #pragma unroll
    for (int k = 0; k < HI_ITER; k++){
        float tv4[4] = {ta[k].x, ta[k].y, ta[k].z, ta[k].w};
        float sv4[4] = {sa[k].x, sa[k].y, sa[k].z, sa[k].w};
        #pragma unroll
        for (int e = 0; e < 4; e++){
            float ut = (tv4[e] - tmin) * tsc;
            float us = (sv4[e] - smin) * ssc;
            int kt = __float2int_rd(ut);
            int ks = __float2int_rd(us);
            float dt = ut - (float)kt;
            float ds = us - (float)ks;
            float wt[4], ws[4];
            #pragma unroll
            for (int j = 0; j < 4; j++){
                float x1 = dt - (float)(j - 1);
                float x2 = ds - (float)(j - 1);
                wt[j] = ((unsigned)(kt + j - 1) < 64u) ? __expf(-CEXP * x1 * x1) : 0.f;
                ws[j] = ((unsigned)(ks + j - 1) < 64u) ? __expf(-CEXP * x2 * x2) : 0.f;
            }
            int bofs = (kt - 1) * SH_STRIDE + (ks - 1);
            #pragma unroll
            for (int jt = 0; jt < 4; jt++){
                if (wt[jt] != 0.f){
                    #pragma unroll
                    for (int js = 0; js < 4; js++){
                        if (ws[js] != 0.f)
                            atomicAdd(&sh[bofs + jt * SH_STRIDE + js], wt[jt] * ws[js]);
                    }
                }
            }
        }
    }
    __syncthreads();
    for (int i = tid; i < HB; i += 512){
        int r = i >> 6, c = i & 63;
        atomicAdd(&g_hist[s][i], sh[r * SH_STRIDE + c]);   // RED.global
    }
}

// ---------------- entropies + loss + state reset ----------------
__global__ void __launch_bounds__(512) k_final(float* __restrict__ out){
    __shared__ float red[2][16];
    __shared__ float mrow[2][64];
    __shared__ float mcol[2][64];
    __shared__ float sS[2], sEJ[2];

    const int tid  = threadIdx.x;
    const int lane = tid & 31;
    const int wid  = tid >> 5;

    if (tid < 128){
        (&mrow[0][0])[tid] = 0.f;
        (&mcol[0][0])[tid] = 0.f;
    }

    float v[2][8];
    float ls[2];
    #pragma unroll
    for (int s = 0; s < 2; s++){
        const float4* h4 = (const float4*)g_hist[s];
        float4 a = h4[tid*2], b = h4[tid*2+1];
        v[s][0]=a.x; v[s][1]=a.y; v[s][2]=a.z; v[s][3]=a.w;
        v[s][4]=b.x; v[s][5]=b.y; v[s][6]=b.z; v[s][7]=b.w;
        ls[s] = ((a.x+a.y)+(a.z+a.w)) + ((b.x+b.y)+(b.z+b.w));
    }
    __syncthreads();

    const int row = tid >> 3;
    const int c0  = (tid & 7) * 8;
    const int rot = (tid >> 3) & 7;
    #pragma unroll
    for (int s = 0; s < 2; s++){
        atomicAdd(&mrow[s][row], ls[s]);
        #pragma unroll
        for (int j = 0; j < 8; j++){
            int jj = (j + rot) & 7;
            atomicAdd(&mcol[s][c0 + jj], v[s][jj]);
        }
    }

    float s0 = wred(ls[0]);
    float s1 = wred(ls[1]);
    if (lane == 0){ red[0][wid] = s0; red[1][wid] = s1; }
    __syncthreads();
    if (tid == 0){
        float t0 = 0.f, t1 = 0.f;
        #pragma unroll
        for (int i = 0; i < 16; i++){ t0 += red[0][i]; t1 += red[1][i]; }
        sS[0] = t0; sS[1] = t1;
    }
    __syncthreads();

    #pragma unroll
    for (int s = 0; s < 2; s++){
        float invS = 1.0f / sS[s];
        float acc = 0.f;
        #pragma unroll
        for (int k = 0; k < 8; k++){
            float p = v[s][k] * invS;
            acc -= p * __logf(p + 1e-10f);
        }
        acc = wred(acc);
        if (lane == 0) red[s][wid] = acc;
    }
    __syncthreads();
    if (tid == 0){
        float e0 = 0.f, e1 = 0.f;
        #pragma unroll
        for (int i = 0; i < 16; i++){ e0 += red[0][i]; e1 += red[1][i]; }
        sEJ[0] = e0; sEJ[1] = e1;
    }
    __syncthreads();

    float em = 0.f;
    if (tid < 256){
        int s = tid >> 7, i = tid & 127;
        float m = (i < 64) ? mrow[s][i] : mcol[s][i - 64];
        float p = m / sS[s];
        em = -p * __logf(p + 1e-10f);
    }
    em = wred(em);
    if (lane == 0) red[0][wid] = em;
    __syncthreads();
    if (tid == 0){
        float em0 = red[0][0]+red[0][1]+red[0][2]+red[0][3];
        float em1 = red[0][4]+red[0][5]+red[0][6]+red[0][7];
        float ratio = em0 / sEJ[0] + em1 / sEJ[1];
        out[0] = -(0.5f * ratio);
    }

    // reset device state for next graph replay
    float4 z = make_float4(0.f, 0.f, 0.f, 0.f);
    float4* h4 = (float4*)&g_hist[0][0];
    #pragma unroll
    for (int k = 0; k < 4; k++) h4[tid * 4 + k] = z;
    if (tid < 8) g_mm[tid] = (tid & 1) ? 0u : 0xFFFFFFFFu;
}

extern "C" void kernel_launch(void* const* d_in, const int* in_sizes, int n_in,
                              void* d_out, int out_size){
    const float* tar = (const float*)d_in[0];
    const float* src = (const float*)d_in[1];
    float* out = (float*)d_out;

    dim3 gmm(MM_BLK, 2);
    k_minmax<<<gmm, 512>>>((const float4*)tar, (const float4*)src);

    dim3 gh(HI_BLK, 2);
    k_hist<<<gh, 512>>>((const float4*)tar, (const float4*)src);

    k_final<<<1, 512>>>(out);
}

// round 4
// speedup vs baseline: 1.7361x; 1.0667x over previous
#include <cuda_runtime.h>
#include <math.h>

#define NPTS (96*96*96)          // 884736 per sample; NPTS/4 = 221184
#define NB   64
#define HB   (NB*NB)
#define SH_STRIDE 65
#define CEXP 2.0639959687578734f // 1/(2*sigma_bins^2) = 8192/3969, sigma = 0.5 bin

// exact factorizations of NPTS/4 = 221184
#define MM_BLK   216
#define MM_ITER  2               // 216*512*2 = 221184
#define HI_BLK   144
#define HI_ITER  3               // 144*512*3 = 221184

__device__ float        g_hist[2][HB];   // zero-initialized at module load
__device__ unsigned int g_mm[8] = {0xFFFFFFFFu, 0u, 0xFFFFFFFFu, 0u,
                                   0xFFFFFFFFu, 0u, 0xFFFFFFFFu, 0u};

__device__ __forceinline__ unsigned fkey(float x){
    unsigned u = __float_as_uint(x);
    return (u & 0x80000000u) ? ~u : (u | 0x80000000u);
}
__device__ __forceinline__ float funkey(unsigned u){
    return (u & 0x80000000u) ? __uint_as_float(u ^ 0x80000000u) : __uint_as_float(~u);
}
__device__ __forceinline__ float wred(float v){
    #pragma unroll
    for (int o = 16; o; o >>= 1) v += __shfl_xor_sync(0xFFFFFFFFu, v, o);
    return v;
}

// ---------------- min/max: 432 CTAs, 4 independent LDG.128/thread ----------------
__global__ void __launch_bounds__(512) k_minmax(const float4* __restrict__ tar,
                                                const float4* __restrict__ src){
    const int s = blockIdx.y;
    const float4* t4 = tar + (size_t)s * (NPTS/4);
    const float4* s4 = src + (size_t)s * (NPTS/4);
    const int base = blockIdx.x * 512 + threadIdx.x;   // stride = 216*512 = 110592

    float4 t0 = __ldg(&t4[base]);
    float4 t1 = __ldg(&t4[base + MM_BLK*512]);
    float4 u0 = __ldg(&s4[base]);
    float4 u1 = __ldg(&s4[base + MM_BLK*512]);

    float tmn = fminf(fminf(fminf(t0.x,t0.y), fminf(t0.z,t0.w)),
                      fminf(fminf(t1.x,t1.y), fminf(t1.z,t1.w)));
    float tmx = fmaxf(fmaxf(fmaxf(t0.x,t0.y), fmaxf(t0.z,t0.w)),
                      fmaxf(fmaxf(t1.x,t1.y), fmaxf(t1.z,t1.w)));
    float smn = fminf(fminf(fminf(u0.x,u0.y), fminf(u0.z,u0.w)),
                      fminf(fminf(u1.x,u1.y), fminf(u1.z,u1.w)));
    float smx = fmaxf(fmaxf(fmaxf(u0.x,u0.y), fmaxf(u0.z,u0.w)),
                      fmaxf(fmaxf(u1.x,u1.y), fmaxf(u1.z,u1.w)));

    #pragma unroll
    for (int o = 16; o; o >>= 1){
        tmn = fminf(tmn, __shfl_xor_sync(0xFFFFFFFFu, tmn, o));
        tmx = fmaxf(tmx, __shfl_xor_sync(0xFFFFFFFFu, tmx, o));
        smn = fminf(smn, __shfl_xor_sync(0xFFFFFFFFu, smn, o));
        smx = fmaxf(smx, __shfl_xor_sync(0xFFFFFFFFu, smx, o));
    }
    if ((threadIdx.x & 31) == 0){
        atomicMin(&g_mm[s*4+0], fkey(tmn));
        atomicMax(&g_mm[s*4+1], fkey(tmx));
        atomicMin(&g_mm[s*4+2], fkey(smn));
        atomicMax(&g_mm[s*4+3], fkey(smx));
    }
}

// ---------------- joint histogram (3x3 round-anchored stencil) ----------------
__global__ void __launch_bounds__(512) k_hist(const float4* __restrict__ tar,
                                              const float4* __restrict__ src){
    __shared__ float sh[NB * SH_STRIDE];
    const int tid = threadIdx.x;
    const int s   = blockIdx.y;
    #pragma unroll
    for (int i = 0; i < 9; i++){
        int j = tid + i * 512;
        if (j < NB * SH_STRIDE) sh[j] = 0.f;
    }
    __syncthreads();

    const float tmin = funkey(g_mm[s*4+0]);
    const float tmax = funkey(g_mm[s*4+1]);
    const float smin = funkey(g_mm[s*4+2]);
    const float smax = funkey(g_mm[s*4+3]);
    const float tsc = 63.0f / (tmax - tmin + 1e-10f);
    const float ssc = 63.0f / (smax - smin + 1e-10f);

    const float4* t4 = tar + (size_t)s * (NPTS/4);
    const float4* s4 = src + (size_t)s * (NPTS/4);
    const int base = blockIdx.x * 512 + tid;           // stride = 144*512 = 73728

    float4 ta[HI_ITER], sa[HI_ITER];
    #pragma unroll
    for (int k = 0; k < HI_ITER; k++){
        ta[k] = __ldg(&t4[base + k * (HI_BLK*512)]);
        sa[k] = __ldg(&s4[base + k * (HI_BLK*512)]);
    }

    #pragma unroll
    for (int k = 0; k < HI_ITER; k++){
        float tv4[4] = {ta[k].x, ta[k].y, ta[k].z, ta[k].w};
        float sv4[4] = {sa[k].x, sa[k].y, sa[k].z, sa[k].w};
        #pragma unroll
        for (int e = 0; e < 4; e++){
            float ut = (tv4[e] - tmin) * tsc;
            float us = (sv4[e] - smin) * ssc;
            int kt = __float2int_rn(ut);               // nearest bin
            int ks = __float2int_rn(us);
            float dt = ut - (float)kt;                 // in [-0.5, 0.5]
            float ds = us - (float)ks;
            float wt[3], ws[3];
            #pragma unroll
            for (int j = 0; j < 3; j++){
                float x1 = dt - (float)(j - 1);
                float x2 = ds - (float)(j - 1);
                wt[j] = ((unsigned)(kt + j - 1) < 64u) ? __expf(-CEXP * x1 * x1) : 0.f;
                ws[j] = ((unsigned)(ks + j - 1) < 64u) ? __expf(-CEXP * x2 * x2) : 0.f;
            }
            int bofs = (kt - 1) * SH_STRIDE + (ks - 1);
            #pragma unroll
            for (int jt = 0; jt < 3; jt++){
                if (wt[jt] != 0.f){
                    #pragma unroll
                    for (int js = 0; js < 3; js++){
                        if (ws[js] != 0.f)
                            atomicAdd(&sh[bofs + jt * SH_STRIDE + js], wt[jt] * ws[js]);
                    }
                }
            }
        }
    }
    __syncthreads();
    for (int i = tid; i < HB; i += 512){
        int r = i >> 6, c = i & 63;
        atomicAdd(&g_hist[s][i], sh[r * SH_STRIDE + c]);   // RED.global
    }
}

// ---------------- entropies + loss + state reset ----------------
__global__ void __launch_bounds__(512) k_final(float* __restrict__ out){
    __shared__ float red[2][16];
    __shared__ float mrow[2][64];
    __shared__ float mcol[2][64];
    __shared__ float sS[2], sEJ[2];

    const int tid  = threadIdx.x;
    const int lane = tid & 31;
    const int wid  = tid >> 5;

    if (tid < 128){
        (&mrow[0][0])[tid] = 0.f;
        (&mcol[0][0])[tid] = 0.f;
    }

    float v[2][8];
    float ls[2];
    #pragma unroll
    for (int s = 0; s < 2; s++){
        const float4* h4 = (const float4*)g_hist[s];
        float4 a = h4[tid*2], b = h4[tid*2+1];
        v[s][0]=a.x; v[s][1]=a.y; v[s][2]=a.z; v[s][3]=a.w;
        v[s][4]=b.x; v[s][5]=b.y; v[s][6]=b.z; v[s][7]=b.w;
        ls[s] = ((a.x+a.y)+(a.z+a.w)) + ((b.x+b.y)+(b.z+b.w));
    }
    __syncthreads();

    const int row = tid >> 3;
    const int c0  = (tid & 7) * 8;
    const int rot = (tid >> 3) & 7;
    #pragma unroll
    for (int s = 0; s < 2; s++){
        atomicAdd(&mrow[s][row], ls[s]);
        #pragma unroll
        for (int j = 0; j < 8; j++){
            int jj = (j + rot) & 7;
            atomicAdd(&mcol[s][c0 + jj], v[s][jj]);
        }
    }

    float s0 = wred(ls[0]);
    float s1 = wred(ls[1]);
    if (lane == 0){ red[0][wid] = s0; red[1][wid] = s1; }
    __syncthreads();
    if (tid == 0){
        float t0 = 0.f, t1 = 0.f;
        #pragma unroll
        for (int i = 0; i < 16; i++){ t0 += red[0][i]; t1 += red[1][i]; }
        sS[0] = t0; sS[1] = t1;
    }
    __syncthreads();

    #pragma unroll
    for (int s = 0; s < 2; s++){
        float invS = 1.0f / sS[s];
        float acc = 0.f;
        #pragma unroll
        for (int k = 0; k < 8; k++){
            float p = v[s][k] * invS;
            acc -= p * __logf(p + 1e-10f);
        }
        acc = wred(acc);
        if (lane == 0) red[s][wid] = acc;
    }
    __syncthreads();
    if (tid == 0){
        float e0 = 0.f, e1 = 0.f;
        #pragma unroll
        for (int i = 0; i < 16; i++){ e0 += red[0][i]; e1 += red[1][i]; }
        sEJ[0] = e0; sEJ[1] = e1;
    }
    __syncthreads();

    float em = 0.f;
    if (tid < 256){
        int s = tid >> 7, i = tid & 127;
        float m = (i < 64) ? mrow[s][i] : mcol[s][i - 64];
        float p = m / sS[s];
        em = -p * __logf(p + 1e-10f);
    }
    em = wred(em);
    if (lane == 0) red[0][wid] = em;
    __syncthreads();
    if (tid == 0){
        float em0 = red[0][0]+red[0][1]+red[0][2]+red[0][3];
        float em1 = red[0][4]+red[0][5]+red[0][6]+red[0][7];
        float ratio = em0 / sEJ[0] + em1 / sEJ[1];
        out[0] = -(0.5f * ratio);
    }

    // reset device state for next graph replay
    float4 z = make_float4(0.f, 0.f, 0.f, 0.f);
    float4* h4 = (float4*)&g_hist[0][0];
    #pragma unroll
    for (int k = 0; k < 4; k++) h4[tid * 4 + k] = z;
    if (tid < 8) g_mm[tid] = (tid & 1) ? 0u : 0xFFFFFFFFu;
}

extern "C" void kernel_launch(void* const* d_in, const int* in_sizes, int n_in,
                              void* d_out, int out_size){
    const float* tar = (const float*)d_in[0];
    const float* src = (const float*)d_in[1];
    float* out = (float*)d_out;

    dim3 gmm(MM_BLK, 2);
    k_minmax<<<gmm, 512>>>((const float4*)tar, (const float4*)src);

    dim3 gh(HI_BLK, 2);
    k_hist<<<gh, 512>>>((const float4*)tar, (const float4*)src);

    k_final<<<1, 512>>>(out);
}

// round 5
// speedup vs baseline: 2.2020x; 1.2683x over previous
#include <cuda_runtime.h>
#include <math.h>

#define NQ   221184              // 96^3 / 4 float4 per sample
#define NB   64
#define HB   (NB*NB)
#define SH_STRIDE 65
#define CEXP 2.0639959687578734f // 1/(2*sigma_bins^2), sigma = 0.5 bin
#define CTAS_X 148
#define NCTA   296               // 148 x 2 samples, co-resident at occ=2
#define STRIDE (CTAS_X*512)      // 75776

__device__ float    g_hist[2][HB];   // zeroed at load; reset each run by CTA(0,0)
__device__ unsigned g_mm[8] = {0xFFFFFFFFu, 0u, 0xFFFFFFFFu, 0u,
                               0xFFFFFFFFu, 0u, 0xFFFFFFFFu, 0u};
__device__ unsigned g_bar1 = 0u, g_bar2 = 0u;

__device__ __forceinline__ unsigned fkey(float x){
    unsigned u = __float_as_uint(x);
    return (u & 0x80000000u) ? ~u : (u | 0x80000000u);
}
__device__ __forceinline__ float funkey(unsigned u){
    return (u & 0x80000000u) ? __uint_as_float(u ^ 0x80000000u) : __uint_as_float(~u);
}
__device__ __forceinline__ float wsum(float v){
    #pragma unroll
    for (int o = 16; o; o >>= 1) v += __shfl_xor_sync(0xFFFFFFFFu, v, o);
    return v;
}

__global__ void __launch_bounds__(512, 2)
k_fused(const float4* __restrict__ tar, const float4* __restrict__ src,
        float* __restrict__ out)
{
    __shared__ float sh[NB * SH_STRIDE];
    __shared__ float rmm[4][16];

    const int tid  = threadIdx.x;
    const int smp  = blockIdx.y;
    const int lane = tid & 31;
    const int wid  = tid >> 5;

    // zero privatized histogram
    #pragma unroll
    for (int i = 0; i < 9; i++){
        int j = tid + i * 512;
        if (j < NB * SH_STRIDE) sh[j] = 0.f;
    }

    // ---------------- phase 1: load once, min/max ----------------
    const float4* t4 = tar + (size_t)smp * NQ;
    const float4* s4 = src + (size_t)smp * NQ;
    const int i0 = blockIdx.x * 512 + tid;

    float4 ta0 = __ldg(&t4[i0]);
    float4 sa0 = __ldg(&s4[i0]);
    float4 ta1 = __ldg(&t4[i0 + STRIDE]);
    float4 sa1 = __ldg(&s4[i0 + STRIDE]);
    const bool v2 = (i0 + 2*STRIDE) < NQ;
    float4 ta2 = make_float4(0.f,0.f,0.f,0.f);
    float4 sa2 = ta2;
    if (v2){ ta2 = __ldg(&t4[i0 + 2*STRIDE]); sa2 = __ldg(&s4[i0 + 2*STRIDE]); }

    float tmn = fminf(fminf(fminf(ta0.x,ta0.y), fminf(ta0.z,ta0.w)),
                      fminf(fminf(ta1.x,ta1.y), fminf(ta1.z,ta1.w)));
    float tmx = fmaxf(fmaxf(fmaxf(ta0.x,ta0.y), fmaxf(ta0.z,ta0.w)),
                      fmaxf(fmaxf(ta1.x,ta1.y), fmaxf(ta1.z,ta1.w)));
    float smn = fminf(fminf(fminf(sa0.x,sa0.y), fminf(sa0.z,sa0.w)),
                      fminf(fminf(sa1.x,sa1.y), fminf(sa1.z,sa1.w)));
    float smx = fmaxf(fmaxf(fmaxf(sa0.x,sa0.y), fmaxf(sa0.z,sa0.w)),
                      fmaxf(fmaxf(sa1.x,sa1.y), fmaxf(sa1.z,sa1.w)));
    if (v2){
        tmn = fminf(tmn, fminf(fminf(ta2.x,ta2.y), fminf(ta2.z,ta2.w)));
        tmx = fmaxf(tmx, fmaxf(fmaxf(ta2.x,ta2.y), fmaxf(ta2.z,ta2.w)));
        smn = fminf(smn, fminf(fminf(sa2.x,sa2.y), fminf(sa2.z,sa2.w)));
        smx = fmaxf(smx, fmaxf(fmaxf(sa2.x,sa2.y), fmaxf(sa2.z,sa2.w)));
    }
    #pragma unroll
    for (int o = 16; o; o >>= 1){
        tmn = fminf(tmn, __shfl_xor_sync(0xFFFFFFFFu, tmn, o));
        tmx = fmaxf(tmx, __shfl_xor_sync(0xFFFFFFFFu, tmx, o));
        smn = fminf(smn, __shfl_xor_sync(0xFFFFFFFFu, smn, o));
        smx = fmaxf(smx, __shfl_xor_sync(0xFFFFFFFFu, smx, o));
    }
    if (lane == 0){ rmm[0][wid]=tmn; rmm[1][wid]=tmx; rmm[2][wid]=smn; rmm[3][wid]=smx; }
    __syncthreads();

    // one atomic set per CTA, then grid barrier #1
    if (tid == 0){
        float a=rmm[0][0], b=rmm[1][0], c=rmm[2][0], d=rmm[3][0];
        #pragma unroll
        for (int i = 1; i < 16; i++){
            a = fminf(a, rmm[0][i]); b = fmaxf(b, rmm[1][i]);
            c = fminf(c, rmm[2][i]); d = fmaxf(d, rmm[3][i]);
        }
        atomicMin(&g_mm[smp*4+0], fkey(a));
        atomicMax(&g_mm[smp*4+1], fkey(b));
        atomicMin(&g_mm[smp*4+2], fkey(c));
        atomicMax(&g_mm[smp*4+3], fkey(d));
        __threadfence();
        atomicAdd(&g_bar1, 1u);
        while (atomicAdd(&g_bar1, 0u) < (unsigned)NCTA) __nanosleep(32);
        __threadfence();
    }
    __syncthreads();

    // ---------------- phase 2: histogram from registers ----------------
    volatile unsigned* vm = g_mm;
    const float tmin = funkey(vm[smp*4+0]);
    const float tmax = funkey(vm[smp*4+1]);
    const float smin = funkey(vm[smp*4+2]);
    const float smax = funkey(vm[smp*4+3]);
    const float tsc = 63.0f / (tmax - tmin + 1e-10f);
    const float ssc = 63.0f / (smax - smin + 1e-10f);

    float4 tv[3] = {ta0, ta1, ta2};
    float4 sv[3] = {sa0, sa1, sa2};
    #pragma unroll
    for (int k = 0; k < 3; k++){
        if (k == 2 && !v2) break;
        float te[4] = {tv[k].x, tv[k].y, tv[k].z, tv[k].w};
        float se[4] = {sv[k].x, sv[k].y, sv[k].z, sv[k].w};
        #pragma unroll
        for (int e = 0; e < 4; e++){
            float ut = (te[e] - tmin) * tsc;
            float us = (se[e] - smin) * ssc;
            int kt = __float2int_rn(ut);
            int ks = __float2int_rn(us);
            float dt = ut - (float)kt;       // [-0.5, 0.5]
            float ds = us - (float)ks;
            float wt[3], ws[3];
            #pragma unroll
            for (int j = 0; j < 3; j++){
                float x1 = dt - (float)(j - 1);
                float x2 = ds - (float)(j - 1);
                wt[j] = ((unsigned)(kt + j - 1) < 64u) ? __expf(-CEXP * x1 * x1) : 0.f;
                ws[j] = ((unsigned)(ks + j - 1) < 64u) ? __expf(-CEXP * x2 * x2) : 0.f;
            }
            int bofs = (kt - 1) * SH_STRIDE + (ks - 1);
            #pragma unroll
            for (int jt = 0; jt < 3; jt++){
                if (wt[jt] != 0.f){
                    #pragma unroll
                    for (int js = 0; js < 3; js++){
                        if (ws[js] != 0.f)
                            atomicAdd(&sh[bofs + jt * SH_STRIDE + js], wt[jt] * ws[js]);
                    }
                }
            }
        }
    }
    __syncthreads();

    // flush to global (RED), then grid barrier #2
    #pragma unroll
    for (int i2 = 0; i2 < 8; i2++){
        int i = tid + i2 * 512;
        int r = i >> 6, c = i & 63;
        atomicAdd(&g_hist[smp][i], sh[r * SH_STRIDE + c]);
    }
    __threadfence();
    __syncthreads();
    if (tid == 0) atomicAdd(&g_bar2, 1u);

    if (blockIdx.x != 0 || smp != 0) return;

    // ---------------- phase 3 (CTA 0 only): entropies + loss + reset ----------------
    if (tid == 0){
        while (atomicAdd(&g_bar2, 0u) < (unsigned)NCTA) __nanosleep(32);
        __threadfence();
    }
    __syncthreads();

    __shared__ float red[2][16];
    __shared__ float mrow[2][64];
    __shared__ float mcol[2][64];
    __shared__ float sS[2], sEJ[2];

    if (tid < 128){
        (&mrow[0][0])[tid] = 0.f;
        (&mcol[0][0])[tid] = 0.f;
    }

    float v[2][8];
    float ls[2];
    #pragma unroll
    for (int s2 = 0; s2 < 2; s2++){
        const float4* h4 = (const float4*)g_hist[s2];
        float4 a = __ldcg(&h4[tid*2]);
        float4 b = __ldcg(&h4[tid*2+1]);
        v[s2][0]=a.x; v[s2][1]=a.y; v[s2][2]=a.z; v[s2][3]=a.w;
        v[s2][4]=b.x; v[s2][5]=b.y; v[s2][6]=b.z; v[s2][7]=b.w;
        ls[s2] = ((a.x+a.y)+(a.z+a.w)) + ((b.x+b.y)+(b.z+b.w));
    }
    __syncthreads();

    const int row = tid >> 3;
    const int c0  = (tid & 7) * 8;
    const int rot = (tid >> 3) & 7;
    #pragma unroll
    for (int s2 = 0; s2 < 2; s2++){
        atomicAdd(&mrow[s2][row], ls[s2]);
        #pragma unroll
        for (int j = 0; j < 8; j++){
            int jj = (j + rot) & 7;
            atomicAdd(&mcol[s2][c0 + jj], v[s2][jj]);
        }
    }

    float s0 = wsum(ls[0]);
    float s1 = wsum(ls[1]);
    if (lane == 0){ red[0][wid] = s0; red[1][wid] = s1; }
    __syncthreads();
    if (tid == 0){
        float t0 = 0.f, t1 = 0.f;
        #pragma unroll
        for (int i = 0; i < 16; i++){ t0 += red[0][i]; t1 += red[1][i]; }
        sS[0] = t0; sS[1] = t1;
    }
    __syncthreads();

    #pragma unroll
    for (int s2 = 0; s2 < 2; s2++){
        float invS = 1.0f / sS[s2];
        float acc = 0.f;
        #pragma unroll
        for (int k = 0; k < 8; k++){
            float p = v[s2][k] * invS;
            acc -= p * __logf(p + 1e-10f);
        }
        acc = wsum(acc);
        if (lane == 0) red[s2][wid] = acc;
    }
    __syncthreads();
    if (tid == 0){
        float e0 = 0.f, e1 = 0.f;
        #pragma unroll
        for (int i = 0; i < 16; i++){ e0 += red[0][i]; e1 += red[1][i]; }
        sEJ[0] = e0; sEJ[1] = e1;
    }
    __syncthreads();

    float em = 0.f;
    if (tid < 256){
        int s2 = tid >> 7, i = tid & 127;
        float m = (i < 64) ? mrow[s2][i] : mcol[s2][i - 64];
        float p = m / sS[s2];
        em = -p * __logf(p + 1e-10f);
    }
    em = wsum(em);
    if (lane == 0) red[0][wid] = em;
    __syncthreads();
    if (tid == 0){
        float em0 = red[0][0]+red[0][1]+red[0][2]+red[0][3];
        float em1 = red[0][4]+red[0][5]+red[0][6]+red[0][7];
        out[0] = -(0.5f * (em0 / sEJ[0] + em1 / sEJ[1]));
    }

    // reset device state for next graph replay
    float4 z = make_float4(0.f, 0.f, 0.f, 0.f);
    float4* h4r = (float4*)&g_hist[0][0];
    #pragma unroll
    for (int k = 0; k < 4; k++) h4r[tid * 4 + k] = z;
    if (tid < 8) g_mm[tid] = (tid & 1) ? 0u : 0xFFFFFFFFu;
    if (tid == 0){ g_bar1 = 0u; g_bar2 = 0u; }
}

extern "C" void kernel_launch(void* const* d_in, const int* in_sizes, int n_in,
                              void* d_out, int out_size){
    const float* tar = (const float*)d_in[0];
    const float* src = (const float*)d_in[1];
    float* out = (float*)d_out;

    dim3 g(CTAS_X, 2);
    k_fused<<<g, 512>>>((const float4*)tar, (const float4*)src, out);
}

// round 7
// speedup vs baseline: 2.2363x; 1.0156x over previous
#include <cuda_runtime.h>
#include <math.h>

#define NQ   221184              // 96^3 / 4 float4 per sample
#define NB   64
#define HB   (NB*NB)
#define PR   66                  // padded rows: guard ring top/bottom
#define PSTR 67                  // padded col stride (66 cols used + 1 bank pad)
#define PSZ  (PR*PSTR)           // 4422 floats = 17.7KB
#define CEXP2 2.9777167f         // (1/(2*sigma_bins^2)) * log2(e)
#define CTAS_X 148
#define NCTA   296
#define STRIDE (CTAS_X*512)      // 75776

__device__ float    g_hist[2][HB];
__device__ unsigned g_mm[8] = {0xFFFFFFFFu, 0u, 0xFFFFFFFFu, 0u,
                               0xFFFFFFFFu, 0u, 0xFFFFFFFFu, 0u};
__device__ unsigned g_bar1 = 0u, g_bar2 = 0u;

__device__ __forceinline__ float ex2(float x){
    float r;
    asm("ex2.approx.ftz.f32 %0, %1;" : "=f"(r) : "f"(x));
    return r;
}
__device__ __forceinline__ unsigned fkey(float x){
    unsigned u = __float_as_uint(x);
    return (u & 0x80000000u) ? ~u : (u | 0x80000000u);
}
__device__ __forceinline__ float funkey(unsigned u){
    return (u & 0x80000000u) ? __uint_as_float(u ^ 0x80000000u) : __uint_as_float(~u);
}
__device__ __forceinline__ float wsum(float v){
    #pragma unroll
    for (int o = 16; o; o >>= 1) v += __shfl_xor_sync(0xFFFFFFFFu, v, o);
    return v;
}

__global__ void __launch_bounds__(512, 2)
k_fused(const float4* __restrict__ tar, const float4* __restrict__ src,
        float* __restrict__ out)
{
    __shared__ float sh[PSZ];
    __shared__ float rmm[4][16];

    const int tid  = threadIdx.x;
    const int smp  = blockIdx.y;
    const int lane = tid & 31;
    const int wid  = tid >> 5;

    // zero padded histogram (guard ring included)
    #pragma unroll
    for (int i = 0; i < 9; i++){
        int j = tid + i * 512;
        if (j < PSZ) sh[j] = 0.f;
    }

    // ---------------- phase 1: load once, min/max ----------------
    const float4* t4 = tar + (size_t)smp * NQ;
    const float4* s4 = src + (size_t)smp * NQ;
    const int i0 = blockIdx.x * 512 + tid;

    float4 ta0 = __ldg(&t4[i0]);
    float4 sa0 = __ldg(&s4[i0]);
    float4 ta1 = __ldg(&t4[i0 + STRIDE]);
    float4 sa1 = __ldg(&s4[i0 + STRIDE]);
    const bool v2 = (i0 + 2*STRIDE) < NQ;
    float4 ta2 = make_float4(0.f,0.f,0.f,0.f);
    float4 sa2 = ta2;
    if (v2){ ta2 = __ldg(&t4[i0 + 2*STRIDE]); sa2 = __ldg(&s4[i0 + 2*STRIDE]); }

    float tmn = fminf(fminf(fminf(ta0.x,ta0.y), fminf(ta0.z,ta0.w)),
                      fminf(fminf(ta1.x,ta1.y), fminf(ta1.z,ta1.w)));
    float tmx = fmaxf(fmaxf(fmaxf(ta0.x,ta0.y), fmaxf(ta0.z,ta0.w)),
                      fmaxf(fmaxf(ta1.x,ta1.y), fmaxf(ta1.z,ta1.w)));
    float smn = fminf(fminf(fminf(sa0.x,sa0.y), fminf(sa0.z,sa0.w)),
                      fminf(fminf(sa1.x,sa1.y), fminf(sa1.z,sa1.w)));
    float smx = fmaxf(fmaxf(fmaxf(sa0.x,sa0.y), fmaxf(sa0.z,sa0.w)),
                      fmaxf(fmaxf(sa1.x,sa1.y), fmaxf(sa1.z,sa1.w)));
    if (v2){
        tmn = fminf(tmn, fminf(fminf(ta2.x,ta2.y), fminf(ta2.z,ta2.w)));
        tmx = fmaxf(tmx, fmaxf(fmaxf(ta2.x,ta2.y), fmaxf(ta2.z,ta2.w)));
        smn = fminf(smn, fminf(fminf(sa2.x,sa2.y), fminf(sa2.z,sa2.w)));
        smx = fmaxf(smx, fmaxf(fmaxf(sa2.x,sa2.y), fmaxf(sa2.z,sa2.w)));
    }
    #pragma unroll
    for (int o = 16; o; o >>= 1){
        tmn = fminf(tmn, __shfl_xor_sync(0xFFFFFFFFu, tmn, o));
        tmx = fmaxf(tmx, __shfl_xor_sync(0xFFFFFFFFu, tmx, o));
        smn = fminf(smn, __shfl_xor_sync(0xFFFFFFFFu, smn, o));
        smx = fmaxf(smx, __shfl_xor_sync(0xFFFFFFFFu, smx, o));
    }
    if (lane == 0){ rmm[0][wid]=tmn; rmm[1][wid]=tmx; rmm[2][wid]=smn; rmm[3][wid]=smx; }
    __syncthreads();

    if (tid == 0){
        float a=rmm[0][0], b=rmm[1][0], c=rmm[2][0], d=rmm[3][0];
        #pragma unroll
        for (int i = 1; i < 16; i++){
            a = fminf(a, rmm[0][i]); b = fmaxf(b, rmm[1][i]);
            c = fminf(c, rmm[2][i]); d = fmaxf(d, rmm[3][i]);
        }
        atomicMin(&g_mm[smp*4+0], fkey(a));
        atomicMax(&g_mm[smp*4+1], fkey(b));
        atomicMin(&g_mm[smp*4+2], fkey(c));
        atomicMax(&g_mm[smp*4+3], fkey(d));
        __threadfence();
        atomicAdd(&g_bar1, 1u);
        while (atomicAdd(&g_bar1, 0u) < (unsigned)NCTA) __nanosleep(32);
        __threadfence();
    }
    __syncthreads();

    // ---------------- phase 2: histogram from registers (branch-free) ----------------
    volatile unsigned* vm = g_mm;
    const float tmin = funkey(vm[smp*4+0]);
    const float tmax = funkey(vm[smp*4+1]);
    const float smin = funkey(vm[smp*4+2]);
    const float smax = funkey(vm[smp*4+3]);
    const float tsc = 63.0f / (tmax - tmin + 1e-10f);
    const float ssc = 63.0f / (smax - smin + 1e-10f);

    float4 tv[3] = {ta0, ta1, ta2};
    float4 sv[3] = {sa0, sa1, sa2};
    #pragma unroll
    for (int k = 0; k < 3; k++){
        if (k == 2 && !v2) break;
        float te[4] = {tv[k].x, tv[k].y, tv[k].z, tv[k].w};
        float se[4] = {sv[k].x, sv[k].y, sv[k].z, sv[k].w};
        #pragma unroll
        for (int e = 0; e < 4; e++){
            float ut = (te[e] - tmin) * tsc;
            float us = (se[e] - smin) * ssc;
            int kt = __float2int_rn(ut);
            int ks = __float2int_rn(us);
            float dt = ut - (float)kt;       // [-0.5, 0.5]
            float ds = us - (float)ks;
            // taps at offsets -1, 0, +1 — always inside padded bounds
            float wt0 = ex2(-CEXP2 * (dt + 1.f) * (dt + 1.f));
            float wt1 = ex2(-CEXP2 * dt * dt);
            float wt2 = ex2(-CEXP2 * (dt - 1.f) * (dt - 1.f));
            float ws0 = ex2(-CEXP2 * (ds + 1.f) * (ds + 1.f));
            float ws1 = ex2(-CEXP2 * ds * ds);
            float ws2 = ex2(-CEXP2 * (ds - 1.f) * (ds - 1.f));
            float* p = &sh[kt * PSTR + ks];  // (kt-1+1)*PSTR + (ks-1+1)
            atomicAdd(p             , wt0 * ws0);
            atomicAdd(p + 1         , wt0 * ws1);
            atomicAdd(p + 2         , wt0 * ws2);
            atomicAdd(p + PSTR      , wt1 * ws0);
            atomicAdd(p + PSTR + 1  , wt1 * ws1);
            atomicAdd(p + PSTR + 2  , wt1 * ws2);
            atomicAdd(p + 2*PSTR    , wt2 * ws0);
            atomicAdd(p + 2*PSTR + 1, wt2 * ws1);
            atomicAdd(p + 2*PSTR + 2, wt2 * ws2);
        }
    }
    __syncthreads();

    // flush interior 64x64 to global (RED), then grid barrier #2
    #pragma unroll
    for (int i2 = 0; i2 < 8; i2++){
        int i = tid + i2 * 512;
        int r = i >> 6, c = i & 63;
        atomicAdd(&g_hist[smp][i], sh[(r + 1) * PSTR + (c + 1)]);
    }
    __threadfence();
    __syncthreads();
    if (tid == 0) atomicAdd(&g_bar2, 1u);

    if (blockIdx.x != 0 || smp != 0) return;

    // ---------------- phase 3 (CTA 0 only): entropies + loss + reset ----------------
    if (tid == 0){
        while (atomicAdd(&g_bar2, 0u) < (unsigned)NCTA) __nanosleep(32);
        __threadfence();
    }
    __syncthreads();

    __shared__ float red[2][16];
    __shared__ float mrow[2][64];
    __shared__ float mcol[2][64];
    __shared__ float sS[2], sEJ[2];

    if (tid < 128){
        (&mrow[0][0])[tid] = 0.f;
        (&mcol[0][0])[tid] = 0.f;
    }

    float v[2][8];
    float ls[2];
    #pragma unroll
    for (int s2 = 0; s2 < 2; s2++){
        const float4* h4 = (const float4*)g_hist[s2];
        float4 a = __ldcg(&h4[tid*2]);
        float4 b = __ldcg(&h4[tid*2+1]);
        v[s2][0]=a.x; v[s2][1]=a.y; v[s2][2]=a.z; v[s2][3]=a.w;
        v[s2][4]=b.x; v[s2][5]=b.y; v[s2][6]=b.z; v[s2][7]=b.w;
        ls[s2] = ((a.x+a.y)+(a.z+a.w)) + ((b.x+b.y)+(b.z+b.w));
    }
    __syncthreads();

    const int row = tid >> 3;
    const int c0  = (tid & 7) * 8;
    const int rot = (tid >> 3) & 7;
    #pragma unroll
    for (int s2 = 0; s2 < 2; s2++){
        atomicAdd(&mrow[s2][row], ls[s2]);
        #pragma unroll
        for (int j = 0; j < 8; j++){
            int jj = (j + rot) & 7;
            atomicAdd(&mcol[s2][c0 + jj], v[s2][jj]);
        }
    }

    float s0 = wsum(ls[0]);
    float s1 = wsum(ls[1]);
    if (lane == 0){ red[0][wid] = s0; red[1][wid] = s1; }
    __syncthreads();
    if (tid == 0){
        float t0 = 0.f, t1 = 0.f;
        #pragma unroll
        for (int i = 0; i < 16; i++){ t0 += red[0][i]; t1 += red[1][i]; }
        sS[0] = t0; sS[1] = t1;
    }
    __syncthreads();

    #pragma unroll
    for (int s2 = 0; s2 < 2; s2++){
        float invS = 1.0f / sS[s2];
        float acc = 0.f;
        #pragma unroll
        for (int k = 0; k < 8; k++){
            float p = v[s2][k] * invS;
            acc -= p * __logf(p + 1e-10f);
        }
        acc = wsum(acc);
        if (lane == 0) red[s2][wid] = acc;
    }
    __syncthreads();
    if (tid == 0){
        float e0 = 0.f, e1 = 0.f;
        #pragma unroll
        for (int i = 0; i < 16; i++){ e0 += red[0][i]; e1 += red[1][i]; }
        sEJ[0] = e0; sEJ[1] = e1;
    }
    __syncthreads();

    float em = 0.f;
    if (tid < 256){
        int s2 = tid >> 7, i = tid & 127;
        float m = (i < 64) ? mrow[s2][i] : mcol[s2][i - 64];
        float p = m / sS[s2];
        em = -p * __logf(p + 1e-10f);
    }
    em = wsum(em);
    if (lane == 0) red[0][wid] = em;
    __syncthreads();
    if (tid == 0){
        float em0 = red[0][0]+red[0][1]+red[0][2]+red[0][3];
        float em1 = red[0][4]+red[0][5]+red[0][6]+red[0][7];
        out[0] = -(0.5f * (em0 / sEJ[0] + em1 / sEJ[1]));
    }

    // reset device state for next graph replay
    float4 z = make_float4(0.f, 0.f, 0.f, 0.f);
    float4* h4r = (float4*)&g_hist[0][0];
    #pragma unroll
    for (int k = 0; k < 4; k++) h4r[tid * 4 + k] = z;
    if (tid < 8) g_mm[tid] = (tid & 1) ? 0u : 0xFFFFFFFFu;
    if (tid == 0){ g_bar1 = 0u; g_bar2 = 0u; }
}

extern "C" void kernel_launch(void* const* d_in, const int* in_sizes, int n_in,
                              void* d_out, int out_size){
    const float* tar = (const float*)d_in[0];
    const float* src = (const float*)d_in[1];
    float* out = (float*)d_out;

    dim3 g(CTAS_X, 2);
    k_fused<<<g, 512>>>((const float4*)tar, (const float4*)src, out);
}

// round 8
// speedup vs baseline: 2.5576x; 1.1437x over previous
#include <cuda_runtime.h>
#include <cuda_fp16.h>
#include <math.h>

#define NQ   221184              // 96^3 / 4 float4 per sample
#define NB   64
#define HB   (NB*NB)
#define PRH  66                  // padded rows (guard top/bottom)
#define PSTRH 70                 // padded half-stride (even for half2 align)
#define PSZH (PRH*PSTRH)         // 4620 halfs = 9240 B
#define CEXP2 2.9777167f         // (1/(2*sigma_bins^2)) * log2(e)
#define CTAS_X 148
#define NCTA   296
#define STRIDE (CTAS_X*512)      // 75776

__device__ float    g_hist[2][HB];
__device__ unsigned g_mm[8] = {0xFFFFFFFFu, 0u, 0xFFFFFFFFu, 0u,
                               0xFFFFFFFFu, 0u, 0xFFFFFFFFu, 0u};
__device__ unsigned g_bar1 = 0u, g_bar2 = 0u;

__device__ __forceinline__ float ex2(float x){
    float r;
    asm("ex2.approx.ftz.f32 %0, %1;" : "=f"(r) : "f"(x));
    return r;
}
__device__ __forceinline__ unsigned fkey(float x){
    unsigned u = __float_as_uint(x);
    return (u & 0x80000000u) ? ~u : (u | 0x80000000u);
}
__device__ __forceinline__ float funkey(unsigned u){
    return (u & 0x80000000u) ? __uint_as_float(u ^ 0x80000000u) : __uint_as_float(~u);
}
__device__ __forceinline__ float wsum(float v){
    #pragma unroll
    for (int o = 16; o; o >>= 1) v += __shfl_xor_sync(0xFFFFFFFFu, v, o);
    return v;
}

__global__ void __launch_bounds__(512, 2)
k_fused(const float4* __restrict__ tar, const float4* __restrict__ src,
        float* __restrict__ out)
{
    __shared__ __half sh[PSZH];
    __shared__ float rmm[4][16];

    const int tid  = threadIdx.x;
    const int smp  = blockIdx.y;
    const int lane = tid & 31;
    const int wid  = tid >> 5;

    // zero padded fp16 histogram
    {
        unsigned* z32 = (unsigned*)sh;
        #pragma unroll
        for (int i = 0; i < 5; i++){
            int j = tid + i * 512;
            if (j < PSZH/2) z32[j] = 0u;
        }
    }

    // ---------------- phase 1: load once, min/max ----------------
    const float4* t4 = tar + (size_t)smp * NQ;
    const float4* s4 = src + (size_t)smp * NQ;
    const int i0 = blockIdx.x * 512 + tid;

    float4 ta0 = __ldg(&t4[i0]);
    float4 sa0 = __ldg(&s4[i0]);
    float4 ta1 = __ldg(&t4[i0 + STRIDE]);
    float4 sa1 = __ldg(&s4[i0 + STRIDE]);
    const bool v2 = (i0 + 2*STRIDE) < NQ;
    float4 ta2 = make_float4(0.f,0.f,0.f,0.f);
    float4 sa2 = ta2;
    if (v2){ ta2 = __ldg(&t4[i0 + 2*STRIDE]); sa2 = __ldg(&s4[i0 + 2*STRIDE]); }

    float tmn = fminf(fminf(fminf(ta0.x,ta0.y), fminf(ta0.z,ta0.w)),
                      fminf(fminf(ta1.x,ta1.y), fminf(ta1.z,ta1.w)));
    float tmx = fmaxf(fmaxf(fmaxf(ta0.x,ta0.y), fmaxf(ta0.z,ta0.w)),
                      fmaxf(fmaxf(ta1.x,ta1.y), fmaxf(ta1.z,ta1.w)));
    float smn = fminf(fminf(fminf(sa0.x,sa0.y), fminf(sa0.z,sa0.w)),
                      fminf(fminf(sa1.x,sa1.y), fminf(sa1.z,sa1.w)));
    float smx = fmaxf(fmaxf(fmaxf(sa0.x,sa0.y), fmaxf(sa0.z,sa0.w)),
                      fmaxf(fmaxf(sa1.x,sa1.y), fmaxf(sa1.z,sa1.w)));
    if (v2){
        tmn = fminf(tmn, fminf(fminf(ta2.x,ta2.y), fminf(ta2.z,ta2.w)));
        tmx = fmaxf(tmx, fmaxf(fmaxf(ta2.x,ta2.y), fmaxf(ta2.z,ta2.w)));
        smn = fminf(smn, fminf(fminf(sa2.x,sa2.y), fminf(sa2.z,sa2.w)));
        smx = fmaxf(smx, fmaxf(fmaxf(sa2.x,sa2.y), fmaxf(sa2.z,sa2.w)));
    }
    #pragma unroll
    for (int o = 16; o; o >>= 1){
        tmn = fminf(tmn, __shfl_xor_sync(0xFFFFFFFFu, tmn, o));
        tmx = fmaxf(tmx, __shfl_xor_sync(0xFFFFFFFFu, tmx, o));
        smn = fminf(smn, __shfl_xor_sync(0xFFFFFFFFu, smn, o));
        smx = fmaxf(smx, __shfl_xor_sync(0xFFFFFFFFu, smx, o));
    }
    if (lane == 0){ rmm[0][wid]=tmn; rmm[1][wid]=tmx; rmm[2][wid]=smn; rmm[3][wid]=smx; }
    __syncthreads();

    if (tid == 0){
        float a=rmm[0][0], b=rmm[1][0], c=rmm[2][0], d=rmm[3][0];
        #pragma unroll
        for (int i = 1; i < 16; i++){
            a = fminf(a, rmm[0][i]); b = fmaxf(b, rmm[1][i]);
            c = fminf(c, rmm[2][i]); d = fmaxf(d, rmm[3][i]);
        }
        atomicMin(&g_mm[smp*4+0], fkey(a));
        atomicMax(&g_mm[smp*4+1], fkey(b));
        atomicMin(&g_mm[smp*4+2], fkey(c));
        atomicMax(&g_mm[smp*4+3], fkey(d));
        __threadfence();
        atomicAdd(&g_bar1, 1u);
        while (atomicAdd(&g_bar1, 0u) < (unsigned)NCTA) __nanosleep(32);
        __threadfence();
    }
    __syncthreads();

    // ---------------- phase 2: histogram, half2 packed atomics ----------------
    volatile unsigned* vm = g_mm;
    const float tmin = funkey(vm[smp*4+0]);
    const float tmax = funkey(vm[smp*4+1]);
    const float smin = funkey(vm[smp*4+2]);
    const float smax = funkey(vm[smp*4+3]);
    const float tsc = 63.0f / (tmax - tmin + 1e-10f);
    const float ssc = 63.0f / (smax - smin + 1e-10f);

    float4 tv[3] = {ta0, ta1, ta2};
    float4 sv[3] = {sa0, sa1, sa2};
    #pragma unroll
    for (int k = 0; k < 3; k++){
        if (k == 2 && !v2) break;
        float te[4] = {tv[k].x, tv[k].y, tv[k].z, tv[k].w};
        float se[4] = {sv[k].x, sv[k].y, sv[k].z, sv[k].w};
        #pragma unroll
        for (int e = 0; e < 4; e++){
            float ut = (te[e] - tmin) * tsc;
            float us = (se[e] - smin) * ssc;
            int kt = __float2int_rn(ut);
            int ks = __float2int_rn(us);
            float dt = ut - (float)kt;       // [-0.5, 0.5]
            float ds = us - (float)ks;
            float wt0 = ex2(-CEXP2 * (dt + 1.f) * (dt + 1.f));
            float wt1 = ex2(-CEXP2 * dt * dt);
            float wt2 = ex2(-CEXP2 * (dt - 1.f) * (dt - 1.f));
            float ws0 = ex2(-CEXP2 * (ds + 1.f) * (ds + 1.f));
            float ws1 = ex2(-CEXP2 * ds * ds);
            float ws2 = ex2(-CEXP2 * (ds - 1.f) * (ds - 1.f));

            // padded start col = ks (interior col ks-1 maps to padded ks)
            // pack 3 col taps into two aligned half2 pairs
            const bool odd = (ks & 1);
            __half2 pA = odd ? __floats2half2_rn(0.f, ws0)
                             : __floats2half2_rn(ws0, ws1);
            __half2 pB = odd ? __floats2half2_rn(ws1, ws2)
                             : __floats2half2_rn(ws2, 0.f);
            const int cb = ks & ~1;          // aligned pair base (padded col)
            __half2 w0h = __floats2half2_rn(wt0, wt0);
            __half2 w1h = __floats2half2_rn(wt1, wt1);
            __half2 w2h = __floats2half2_rn(wt2, wt2);

            __half2* p0 = (__half2*)&sh[(kt    ) * PSTRH + cb]; // padded row kt (= interior kt-1)
            __half2* p1 = (__half2*)&sh[(kt + 1) * PSTRH + cb];
            __half2* p2 = (__half2*)&sh[(kt + 2) * PSTRH + cb];
            atomicAdd(p0    , __hmul2(w0h, pA));
            atomicAdd(p0 + 1, __hmul2(w0h, pB));
            atomicAdd(p1    , __hmul2(w1h, pA));
            atomicAdd(p1 + 1, __hmul2(w1h, pB));
            atomicAdd(p2    , __hmul2(w2h, pA));
            atomicAdd(p2 + 1, __hmul2(w2h, pB));
        }
    }
    __syncthreads();

    // flush interior 64x64 (half -> float) to global RED, then grid barrier #2
    #pragma unroll
    for (int i2 = 0; i2 < 8; i2++){
        int i = tid + i2 * 512;
        int r = i >> 6, c = i & 63;
        float val = __half2float(sh[(r + 1) * PSTRH + (c + 1)]);
        atomicAdd(&g_hist[smp][i], val);
    }
    __threadfence();
    __syncthreads();
    if (tid == 0) atomicAdd(&g_bar2, 1u);

    if (blockIdx.x != 0 || smp != 0) return;

    // ---------------- phase 3 (CTA 0 only): entropies + loss + reset ----------------
    if (tid == 0){
        while (atomicAdd(&g_bar2, 0u) < (unsigned)NCTA) __nanosleep(32);
        __threadfence();
    }
    __syncthreads();

    __shared__ float red[2][16];
    __shared__ float mrow[2][64];
    __shared__ float mcol[2][64];
    __shared__ float sS[2], sEJ[2];

    if (tid < 128){
        (&mrow[0][0])[tid] = 0.f;
        (&mcol[0][0])[tid] = 0.f;
    }

    float v[2][8];
    float ls[2];
    #pragma unroll
    for (int s2 = 0; s2 < 2; s2++){
        const float4* h4 = (const float4*)g_hist[s2];
        float4 a = __ldcg(&h4[tid*2]);
        float4 b = __ldcg(&h4[tid*2+1]);
        v[s2][0]=a.x; v[s2][1]=a.y; v[s2][2]=a.z; v[s2][3]=a.w;
        v[s2][4]=b.x; v[s2][5]=b.y; v[s2][6]=b.z; v[s2][7]=b.w;
        ls[s2] = ((a.x+a.y)+(a.z+a.w)) + ((b.x+b.y)+(b.z+b.w));
    }
    __syncthreads();

    const int row = tid >> 3;
    const int c0  = (tid & 7) * 8;
    const int rot = (tid >> 3) & 7;
    #pragma unroll
    for (int s2 = 0; s2 < 2; s2++){
        atomicAdd(&mrow[s2][row], ls[s2]);
        #pragma unroll
        for (int j = 0; j < 8; j++){
            int jj = (j + rot) & 7;
            atomicAdd(&mcol[s2][c0 + jj], v[s2][jj]);
        }
    }

    float s0 = wsum(ls[0]);
    float s1 = wsum(ls[1]);
    if (lane == 0){ red[0][wid] = s0; red[1][wid] = s1; }
    __syncthreads();
    if (tid == 0){
        float t0 = 0.f, t1 = 0.f;
        #pragma unroll
        for (int i = 0; i < 16; i++){ t0 += red[0][i]; t1 += red[1][i]; }
        sS[0] = t0; sS[1] = t1;
    }
    __syncthreads();

    #pragma unroll
    for (int s2 = 0; s2 < 2; s2++){
        float invS = 1.0f / sS[s2];
        float acc = 0.f;
        #pragma unroll
        for (int k = 0; k < 8; k++){
            float p = v[s2][k] * invS;
            acc -= p * __logf(p + 1e-10f);
        }
        acc = wsum(acc);
        if (lane == 0) red[s2][wid] = acc;
    }
    __syncthreads();
    if (tid == 0){
        float e0 = 0.f, e1 = 0.f;
        #pragma unroll
        for (int i = 0; i < 16; i++){ e0 += red[0][i]; e1 += red[1][i]; }
        sEJ[0] = e0; sEJ[1] = e1;
    }
    __syncthreads();

    float em = 0.f;
    if (tid < 256){
        int s2 = tid >> 7, i = tid & 127;
        float m = (i < 64) ? mrow[s2][i] : mcol[s2][i - 64];
        float p = m / sS[s2];
        em = -p * __logf(p + 1e-10f);
    }
    em = wsum(em);
    if (lane == 0) red[0][wid] = em;
    __syncthreads();
    if (tid == 0){
        float em0 = red[0][0]+red[0][1]+red[0][2]+red[0][3];
        float em1 = red[0][4]+red[0][5]+red[0][6]+red[0][7];
        out[0] = -(0.5f * (em0 / sEJ[0] + em1 / sEJ[1]));
    }

    // reset device state for next graph replay
    float4 z = make_float4(0.f, 0.f, 0.f, 0.f);
    float4* h4r = (float4*)&g_hist[0][0];
    #pragma unroll
    for (int k = 0; k < 4; k++) h4r[tid * 4 + k] = z;
    if (tid < 8) g_mm[tid] = (tid & 1) ? 0u : 0xFFFFFFFFu;
    if (tid == 0){ g_bar1 = 0u; g_bar2 = 0u; }
}

extern "C" void kernel_launch(void* const* d_in, const int* in_sizes, int n_in,
                              void* d_out, int out_size){
    const float* tar = (const float*)d_in[0];
    const float* src = (const float*)d_in[1];
    float* out = (float*)d_out;

    dim3 g(CTAS_X, 2);
    k_fused<<<g, 512>>>((const float4*)tar, (const float4*)src, out);
}

// round 9
// speedup vs baseline: 2.6771x; 1.0467x over previous
#include <cuda_runtime.h>
#include <cuda_fp16.h>
#include <math.h>

#define NQ   221184              // 96^3 / 4 float4 per sample
#define NB   64
#define PRH  66                  // padded rows (1 guard row top/bottom + 64)
#define PSTRH 70                 // padded half-stride (even; 2 left guard cols, 64 interior, right guards)
#define PSZH (PRH*PSTRH)         // 4620 halfs per replica
#define CEXP2 2.9777167f         // (1/(2*sigma_bins^2)) * log2(e)
#define CTAS_X 148
#define NCTA   296
#define STRIDE (CTAS_X*512)      // 75776

__device__ __half2  g_hist2[2][2048];   // fp16 global joint hist (2 samples x 64x64)
__device__ unsigned g_mm[8] = {0xFFFFFFFFu, 0u, 0xFFFFFFFFu, 0u,
                               0xFFFFFFFFu, 0u, 0xFFFFFFFFu, 0u};
__device__ unsigned g_bar1 = 0u, g_tick = 0u;

__device__ __forceinline__ float ex2(float x){
    float r;
    asm("ex2.approx.ftz.f32 %0, %1;" : "=f"(r) : "f"(x));
    return r;
}
__device__ __forceinline__ unsigned fkey(float x){
    unsigned u = __float_as_uint(x);
    return (u & 0x80000000u) ? ~u : (u | 0x80000000u);
}
__device__ __forceinline__ float funkey(unsigned u){
    return (u & 0x80000000u) ? __uint_as_float(u ^ 0x80000000u) : __uint_as_float(~u);
}
__device__ __forceinline__ float wsum(float v){
    #pragma unroll
    for (int o = 16; o; o >>= 1) v += __shfl_xor_sync(0xFFFFFFFFu, v, o);
    return v;
}

__global__ void __launch_bounds__(512, 2)
k_fused(const float4* __restrict__ tar, const float4* __restrict__ src,
        float* __restrict__ out)
{
    __shared__ __half shh[2][PSZH];      // two replicas (warps 0-7 / 8-15)
    __shared__ float rmm[4][16];
    __shared__ int   amlast;

    const int tid  = threadIdx.x;
    const int smp  = blockIdx.y;
    const int lane = tid & 31;
    const int wid  = tid >> 5;
    const int rep  = (tid >= 256) ? 1 : 0;

    // zero both fp16 replicas
    {
        unsigned* z32 = (unsigned*)&shh[0][0];
        #pragma unroll
        for (int i = 0; i < 10; i++){
            int j = tid + i * 512;
            if (j < PSZH) z32[j] = 0u;   // PSZH halfs *2 replicas / 2 per word = PSZH words
        }
    }

    // ---------------- phase 1: load once, min/max ----------------
    const float4* t4 = tar + (size_t)smp * NQ;
    const float4* s4 = src + (size_t)smp * NQ;
    const int i0 = blockIdx.x * 512 + tid;

    float4 ta0 = __ldg(&t4[i0]);
    float4 sa0 = __ldg(&s4[i0]);
    float4 ta1 = __ldg(&t4[i0 + STRIDE]);
    float4 sa1 = __ldg(&s4[i0 + STRIDE]);
    const bool v2 = (i0 + 2*STRIDE) < NQ;
    float4 ta2 = make_float4(0.f,0.f,0.f,0.f);
    float4 sa2 = ta2;
    if (v2){ ta2 = __ldg(&t4[i0 + 2*STRIDE]); sa2 = __ldg(&s4[i0 + 2*STRIDE]); }

    float tmn = fminf(fminf(fminf(ta0.x,ta0.y), fminf(ta0.z,ta0.w)),
                      fminf(fminf(ta1.x,ta1.y), fminf(ta1.z,ta1.w)));
    float tmx = fmaxf(fmaxf(fmaxf(ta0.x,ta0.y), fmaxf(ta0.z,ta0.w)),
                      fmaxf(fmaxf(ta1.x,ta1.y), fmaxf(ta1.z,ta1.w)));
    float smn = fminf(fminf(fminf(sa0.x,sa0.y), fminf(sa0.z,sa0.w)),
                      fminf(fminf(sa1.x,sa1.y), fminf(sa1.z,sa1.w)));
    float smx = fmaxf(fmaxf(fmaxf(sa0.x,sa0.y), fmaxf(sa0.z,sa0.w)),
                      fmaxf(fmaxf(sa1.x,sa1.y), fmaxf(sa1.z,sa1.w)));
    if (v2){
        tmn = fminf(tmn, fminf(fminf(ta2.x,ta2.y), fminf(ta2.z,ta2.w)));
        tmx = fmaxf(tmx, fmaxf(fmaxf(ta2.x,ta2.y), fmaxf(ta2.z,ta2.w)));
        smn = fminf(smn, fminf(fminf(sa2.x,sa2.y), fminf(sa2.z,sa2.w)));
        smx = fmaxf(smx, fmaxf(fmaxf(sa2.x,sa2.y), fmaxf(sa2.z,sa2.w)));
    }
    #pragma unroll
    for (int o = 16; o; o >>= 1){
        tmn = fminf(tmn, __shfl_xor_sync(0xFFFFFFFFu, tmn, o));
        tmx = fmaxf(tmx, __shfl_xor_sync(0xFFFFFFFFu, tmx, o));
        smn = fminf(smn, __shfl_xor_sync(0xFFFFFFFFu, smn, o));
        smx = fmaxf(smx, __shfl_xor_sync(0xFFFFFFFFu, smx, o));
    }
    if (lane == 0){ rmm[0][wid]=tmn; rmm[1][wid]=tmx; rmm[2][wid]=smn; rmm[3][wid]=smx; }
    __syncthreads();

    if (tid == 0){
        float a=rmm[0][0], b=rmm[1][0], c=rmm[2][0], d=rmm[3][0];
        #pragma unroll
        for (int i = 1; i < 16; i++){
            a = fminf(a, rmm[0][i]); b = fmaxf(b, rmm[1][i]);
            c = fminf(c, rmm[2][i]); d = fmaxf(d, rmm[3][i]);
        }
        atomicMin(&g_mm[smp*4+0], fkey(a));
        atomicMax(&g_mm[smp*4+1], fkey(b));
        atomicMin(&g_mm[smp*4+2], fkey(c));
        atomicMax(&g_mm[smp*4+3], fkey(d));
        __threadfence();
        atomicAdd(&g_bar1, 1u);
        while (atomicAdd(&g_bar1, 0u) < (unsigned)NCTA) __nanosleep(32);
        __threadfence();
    }
    __syncthreads();

    // ---------------- phase 2: histogram, half2 packed atomics ----------------
    volatile unsigned* vm = g_mm;
    const float tmin = funkey(vm[smp*4+0]);
    const float tmax = funkey(vm[smp*4+1]);
    const float smin = funkey(vm[smp*4+2]);
    const float smax = funkey(vm[smp*4+3]);
    const float tsc = 63.0f / (tmax - tmin + 1e-10f);
    const float ssc = 63.0f / (smax - smin + 1e-10f);

    __half* shp = &shh[rep][0];

    float4 tv[3] = {ta0, ta1, ta2};
    float4 sv[3] = {sa0, sa1, sa2};
    #pragma unroll
    for (int k = 0; k < 3; k++){
        if (k == 2 && !v2) break;
        float te[4] = {tv[k].x, tv[k].y, tv[k].z, tv[k].w};
        float se[4] = {sv[k].x, sv[k].y, sv[k].z, sv[k].w};
        #pragma unroll
        for (int e = 0; e < 4; e++){
            float ut = (te[e] - tmin) * tsc;
            float us = (se[e] - smin) * ssc;
            int kt = __float2int_rn(ut);
            int ks = __float2int_rn(us);
            float dt = ut - (float)kt;       // [-0.5, 0.5]
            float ds = us - (float)ks;
            float wt0 = ex2(-CEXP2 * (dt + 1.f) * (dt + 1.f));
            float wt1 = ex2(-CEXP2 * dt * dt);
            float wt2 = ex2(-CEXP2 * (dt - 1.f) * (dt - 1.f));
            float ws0 = ex2(-CEXP2 * (ds + 1.f) * (ds + 1.f));
            float ws1 = ex2(-CEXP2 * ds * ds);
            float ws2 = ex2(-CEXP2 * (ds - 1.f) * (ds - 1.f));

            // interior col j -> padded col j+2; taps at padded cols ks+1..ks+3
            const int pc = ks + 1;
            const bool odd = (pc & 1);
            __half2 pA = odd ? __floats2half2_rn(0.f, ws0)
                             : __floats2half2_rn(ws0, ws1);
            __half2 pB = odd ? __floats2half2_rn(ws1, ws2)
                             : __floats2half2_rn(ws2, 0.f);
            const int cb = pc & ~1;
            __half2 w0h = __floats2half2_rn(wt0, wt0);
            __half2 w1h = __floats2half2_rn(wt1, wt1);
            __half2 w2h = __floats2half2_rn(wt2, wt2);

            // interior row r -> padded row r+1; taps at padded rows kt..kt+2
            __half2* p0 = (__half2*)&shp[(kt    ) * PSTRH + cb];
            __half2* p1 = (__half2*)&shp[(kt + 1) * PSTRH + cb];
            __half2* p2 = (__half2*)&shp[(kt + 2) * PSTRH + cb];
            atomicAdd(p0    , __hmul2(w0h, pA));
            atomicAdd(p0 + 1, __hmul2(w0h, pB));
            atomicAdd(p1    , __hmul2(w1h, pA));
            atomicAdd(p1 + 1, __hmul2(w1h, pB));
            atomicAdd(p2    , __hmul2(w2h, pA));
            atomicAdd(p2 + 1, __hmul2(w2h, pB));
        }
    }
    __syncthreads();

    // flush interior 64x64: combine replicas, half2 global RED (4 per thread)
    #pragma unroll
    for (int i2 = 0; i2 < 4; i2++){
        int idx = tid + i2 * 512;          // 0..2047 half2 pairs
        int r = idx >> 5;                  // interior row
        int c = (idx & 31) * 2;            // interior col (even)
        int po = (r + 1) * PSTRH + (c + 2);
        __half2 a = *(__half2*)&shh[0][po];
        __half2 b = *(__half2*)&shh[1][po];
        atomicAdd(&g_hist2[smp][idx], __hadd2(a, b));
    }
    __threadfence();
    __syncthreads();

    // ticket: last CTA through does phase 3
    if (tid == 0){
        unsigned old = atomicAdd(&g_tick, 1u);
        amlast = (old == (unsigned)(NCTA - 1));
    }
    __syncthreads();
    if (!amlast) return;
    __threadfence();   // acquire: see all other CTAs' REDs

    // ---------------- phase 3 (last CTA): entropies + loss + reset ----------------
    __shared__ float red[2][16];
    __shared__ float mrow[2][64];
    __shared__ float mcol[2][64];
    __shared__ float sS[2], sEJ[2];

    if (tid < 128){
        (&mrow[0][0])[tid] = 0.f;
        (&mcol[0][0])[tid] = 0.f;
    }

    float v[2][8];
    float ls[2];
    #pragma unroll
    for (int s2 = 0; s2 < 2; s2++){
        const uint4* gh = (const uint4*)g_hist2[s2];
        uint4 q = __ldcg(&gh[tid]);        // 8 halfs = 8 bins
        __half2 h0 = *(__half2*)&q.x;
        __half2 h1 = *(__half2*)&q.y;
        __half2 h2 = *(__half2*)&q.z;
        __half2 h3 = *(__half2*)&q.w;
        v[s2][0] = __low2float(h0);  v[s2][1] = __high2float(h0);
        v[s2][2] = __low2float(h1);  v[s2][3] = __high2float(h1);
        v[s2][4] = __low2float(h2);  v[s2][5] = __high2float(h2);
        v[s2][6] = __low2float(h3);  v[s2][7] = __high2float(h3);
        ls[s2] = ((v[s2][0]+v[s2][1])+(v[s2][2]+v[s2][3]))
               + ((v[s2][4]+v[s2][5])+(v[s2][6]+v[s2][7]));
    }
    __syncthreads();

    const int row = tid >> 3;
    const int c0  = (tid & 7) * 8;
    const int rot = (tid >> 3) & 7;
    #pragma unroll
    for (int s2 = 0; s2 < 2; s2++){
        atomicAdd(&mrow[s2][row], ls[s2]);
        #pragma unroll
        for (int j = 0; j < 8; j++){
            int jj = (j + rot) & 7;
            atomicAdd(&mcol[s2][c0 + jj], v[s2][jj]);
        }
    }

    float s0 = wsum(ls[0]);
    float s1 = wsum(ls[1]);
    if (lane == 0){ red[0][wid] = s0; red[1][wid] = s1; }
    __syncthreads();
    if (tid == 0){
        float t0 = 0.f, t1 = 0.f;
        #pragma unroll
        for (int i = 0; i < 16; i++){ t0 += red[0][i]; t1 += red[1][i]; }
        sS[0] = t0; sS[1] = t1;
    }
    __syncthreads();

    #pragma unroll
    for (int s2 = 0; s2 < 2; s2++){
        float invS = 1.0f / sS[s2];
        float acc = 0.f;
        #pragma unroll
        for (int k = 0; k < 8; k++){
            float p = v[s2][k] * invS;
            acc -= p * __logf(p + 1e-10f);
        }
        acc = wsum(acc);
        if (lane == 0) red[s2][wid] = acc;
    }
    __syncthreads();
    if (tid == 0){
        float e0 = 0.f, e1 = 0.f;
        #pragma unroll
        for (int i = 0; i < 16; i++){ e0 += red[0][i]; e1 += red[1][i]; }
        sEJ[0] = e0; sEJ[1] = e1;
    }
    __syncthreads();

    float em = 0.f;
    if (tid < 256){
        int s2 = tid >> 7, i = tid & 127;
        float m = (i < 64) ? mrow[s2][i] : mcol[s2][i - 64];
        float p = m / sS[s2];
        em = -p * __logf(p + 1e-10f);
    }
    em = wsum(em);
    if (lane == 0) red[0][wid] = em;
    __syncthreads();
    if (tid == 0){
        float em0 = red[0][0]+red[0][1]+red[0][2]+red[0][3];
        float em1 = red[0][4]+red[0][5]+red[0][6]+red[0][7];
        out[0] = -(0.5f * (em0 / sEJ[0] + em1 / sEJ[1]));
    }

    // reset device state for next graph replay
    {
        uint4 z = make_uint4(0u,0u,0u,0u);
        uint4* hz = (uint4*)&g_hist2[0][0];   // 2*2048 half2 = 4096 words = 1024 uint4
        #pragma unroll
        for (int k = 0; k < 2; k++){
            int j = tid + k * 512;
            if (j < 1024) hz[j] = z;
        }
        if (tid < 8) g_mm[tid] = (tid & 1) ? 0u : 0xFFFFFFFFu;
        if (tid == 0){ g_bar1 = 0u; g_tick = 0u; }
    }
}

extern "C" void kernel_launch(void* const* d_in, const int* in_sizes, int n_in,
                              void* d_out, int out_size){
    const float* tar = (const float*)d_in[0];
    const float* src = (const float*)d_in[1];
    float* out = (float*)d_out;

    dim3 g(CTAS_X, 2);
    k_fused<<<g, 512>>>((const float4*)tar, (const float4*)src, out);
}